// round 12
// baseline (speedup 1.0000x reference)
#include <cuda_runtime.h>
#include <cstdint>
#include <math.h>

#define T_DIRS 384
#define N_PTS  384
#define RES    384
#define D1     128
#define D2     32
#define NCELL  387    // cell idx 0..386 (cell -1 .. 385, +1 offset)
#define NW     12     // warps per block
#define G      3      // directions per block
#define GRID   (T_DIRS / G)   // 128 blocks
#define CHUNK  16     // X columns staged per chunk
#define PADK   19     // smem row stride (odd, coprime 32 -> conflict-free)

__device__ unsigned long long g_acc;   // zero-init at load; reset by finalizer
__device__ unsigned int g_done;

// ---------------- Threefry-2x32 (JAX), key = (0, 42) ----------------
__device__ __forceinline__ uint32_t rotl32(uint32_t x, int r) {
    return (x << r) | (x >> (32 - r));
}

__device__ __forceinline__ void threefry2x32_42(uint32_t c0, uint32_t c1,
                                                uint32_t& o0, uint32_t& o1) {
    const uint32_t k0 = 0u, k1 = 42u;
    const uint32_t k2 = 0x1BD11BDAu ^ k0 ^ k1;
    uint32_t x0 = c0 + k0, x1 = c1 + k1;
#define TF_GROUP(r0, r1, r2, r3, ka, kb, inc)                  \
    x0 += x1; x1 = rotl32(x1, r0); x1 ^= x0;                   \
    x0 += x1; x1 = rotl32(x1, r1); x1 ^= x0;                   \
    x0 += x1; x1 = rotl32(x1, r2); x1 ^= x0;                   \
    x0 += x1; x1 = rotl32(x1, r3); x1 ^= x0;                   \
    x0 += (ka); x1 += (kb) + (inc);
    TF_GROUP(13, 15, 26, 6,  k1, k2, 1u)
    TF_GROUP(17, 29, 16, 24, k2, k0, 2u)
    TF_GROUP(13, 15, 26, 6,  k0, k1, 3u)
    TF_GROUP(17, 29, 16, 24, k1, k2, 4u)
    TF_GROUP(13, 15, 26, 6,  k2, k0, 5u)
#undef TF_GROUP
    o0 = x0; o1 = x1;
}

// ---------------- XLA ErfInv (f32, Giles) ----------------
__device__ __forceinline__ float erfinv_xla(float x) {
    float w = -log1pf(-x * x);
    float p;
    if (w < 5.0f) {
        w -= 2.5f;
        p = 2.81022636e-08f;
        p = fmaf(p, w, 3.43273939e-07f);
        p = fmaf(p, w, -3.5233877e-06f);
        p = fmaf(p, w, -4.39150654e-06f);
        p = fmaf(p, w, 0.00021858087f);
        p = fmaf(p, w, -0.00125372503f);
        p = fmaf(p, w, -0.00417768164f);
        p = fmaf(p, w, 0.246640727f);
        p = fmaf(p, w, 1.50140941f);
    } else {
        w = sqrtf(w) - 3.0f;
        p = -0.000200214257f;
        p = fmaf(p, w, 0.000100950558f);
        p = fmaf(p, w, 0.00134934322f);
        p = fmaf(p, w, -0.00367342844f);
        p = fmaf(p, w, 0.00573950773f);
        p = fmaf(p, w, -0.0076224613f);
        p = fmaf(p, w, 0.00943887047f);
        p = fmaf(p, w, 1.00167406f);
        p = fmaf(p, w, 2.83297682f);
    }
    return p * x;
}

// Partitionable threefry: counter (0, j), 32-bit draw = y0 ^ y1.
__device__ __forceinline__ float jax_normal_elem(uint32_t j) {
    uint32_t o0, o1;
    threefry2x32_42(0u, j, o0, o1);
    uint32_t bits = o0 ^ o1;
    uint32_t fb = (bits >> 9) | 0x3f800000u;
    float f = __uint_as_float(fb) - 1.0f;
    const float lo = -0.99999994f;
    float u = f * 2.0f + lo;
    u = fmaxf(lo, u);
    return 1.41421356f * erfinv_xla(u);
}

// ===================== Single fused kernel =====================
// grid = 128 blocks (3 directions each), 384 threads (thread = point n / threshold r).
__global__ void __launch_bounds__(384) fused_kernel(const float* __restrict__ x1,
                                                    const float* __restrict__ x2,
                                                    float* __restrict__ out,
                                                    int out_size) {
    __shared__ float xs[N_PTS * PADK];            // 29184 B X staging
    __shared__ float v1s[G * D1];                 // 1536 B
    __shared__ float v2s[G * D2];                 // 384 B
    __shared__ unsigned short wpc[NW * NCELL];    // 9288 B per-warp cell counts
    __shared__ int   hh[NCELL];                   // 1548 B
    __shared__ int   P[NCELL + 1];                // 1552 B
    __shared__ float b[N_PTS];                    // 1536 B bucketed values
    __shared__ float red[RES];                    // 1536 B
    __shared__ float nrm_s[2 * G];
    __shared__ int   wsum[NW];

    const int tid  = threadIdx.x;
    const int t0   = blockIdx.x * G;
    const int lane = tid & 31;
    const int wid  = tid >> 5;

    // ---------- Phase A: generate G direction columns for both spaces ----------
    {   // v1: G*D1 = 384 values, one per thread
        int g = tid >> 7, i = tid & 127;
        v1s[tid] = jax_normal_elem((uint32_t)(i * T_DIRS + (t0 + g)));
        if (tid < G * D2) {                       // v2: 96 values
            int g2 = tid >> 5, i2 = tid & 31;
            v2s[tid] = jax_normal_elem((uint32_t)(i2 * T_DIRS + (t0 + g2)));
        }
    }
    __syncthreads();
    // norms: warps 0..2 -> v1 col g, warps 3..5 -> v2 col g
    if (wid < 2 * G) {
        float sq = 0.0f;
        if (wid < G) {
#pragma unroll
            for (int j = 0; j < 4; ++j) {
                float v = v1s[wid * D1 + lane + 32 * j];
                sq = fmaf(v, v, sq);
            }
        } else {
            float v = v2s[(wid - G) * D2 + lane];
            sq = v * v;
        }
#pragma unroll
        for (int o = 16; o; o >>= 1) sq += __shfl_xor_sync(0xffffffffu, sq, o);
        if (lane == 0) nrm_s[wid] = sqrtf(sq);
    }
    __syncthreads();
    // normalize in smem
    {
        int g = tid >> 7;
        v1s[tid] = v1s[tid] / nrm_s[g];
        if (tid < G * D2) {
            int g2 = tid >> 5;
            v2s[tid] = v2s[tid] / nrm_s[G + g2];
        }
    }
    __syncthreads();

    // ---------- Phase B: projections nh[g] for this thread's point ----------
    float acc1[G], acc2[G];
#pragma unroll
    for (int g = 0; g < G; ++g) { acc1[g] = 0.0f; acc2[g] = 0.0f; }

    // space1: 8 chunks of 16 columns
    for (int c = 0; c < D1 / CHUNK; ++c) {
        {   // cooperative load: 1536 float4, coalesced
            for (int f = tid; f < N_PTS * (CHUNK / 4); f += 384) {
                int n = f >> 2, q = f & 3;
                float4 v = __ldg(reinterpret_cast<const float4*>(
                                     x1 + n * D1 + c * CHUNK) + q);
                float* dst = &xs[n * PADK + q * 4];
                dst[0] = v.x; dst[1] = v.y; dst[2] = v.z; dst[3] = v.w;
            }
        }
        __syncthreads();
#pragma unroll
        for (int k = 0; k < CHUNK; ++k) {
            float xv = xs[tid * PADK + k];
            int kk = c * CHUNK + k;
#pragma unroll
            for (int g = 0; g < G; ++g)
                acc1[g] = fmaf(xv, v1s[g * D1 + kk], acc1[g]);
        }
        __syncthreads();
    }
    // space2: 2 chunks of 16 columns
    for (int c = 0; c < D2 / CHUNK; ++c) {
        {
            for (int f = tid; f < N_PTS * (CHUNK / 4); f += 384) {
                int n = f >> 2, q = f & 3;
                float4 v = __ldg(reinterpret_cast<const float4*>(
                                     x2 + n * D2 + c * CHUNK) + q);
                float* dst = &xs[n * PADK + q * 4];
                dst[0] = v.x; dst[1] = v.y; dst[2] = v.z; dst[3] = v.w;
            }
        }
        __syncthreads();
#pragma unroll
        for (int k = 0; k < CHUNK; ++k) {
            float xv = xs[tid * PADK + k];
            int kk = c * CHUNK + k;
#pragma unroll
            for (int g = 0; g < G; ++g)
                acc2[g] = fmaf(xv, v2s[g * D2 + kk], acc2[g]);
        }
        __syncthreads();
    }

    // ---------- Phase C/D: per-direction counting-sort ECT + loss ----------
    // bucket pass: deterministic counting sort into threshold-grid cells
#define ECT_BUCKET_PASS(NH)                                                   \
    {                                                                         \
        for (int i = tid; i < (NW * NCELL) / 2; i += 384)                     \
            reinterpret_cast<int*>(wpc)[i] = 0;                               \
        __syncthreads();                                                      \
        int cc  = (int)floorf((NH + 1.0f) * 191.5f);                          \
        idx = min(max(cc, -1), 385) + 1;                                      \
        unsigned mmask = __match_any_sync(0xffffffffu, idx);                  \
        int leader = __ffs(mmask) - 1;                                        \
        rank = __popc(mmask & ((1u << lane) - 1u));                           \
        if (lane == leader)                                                   \
            wpc[wid * NCELL + idx] = (unsigned short)__popc(mmask);           \
        __syncthreads();                                                      \
        for (int i = tid; i < NCELL; i += 384) {                              \
            int ssum = 0;                                                     \
            _Pragma("unroll")                                                 \
            for (int w = 0; w < NW; ++w) ssum += (int)wpc[w * NCELL + i];     \
            hh[i] = ssum;                                                     \
        }                                                                     \
        __syncthreads();                                                      \
        {                                                                     \
            int xv = hh[tid];                                                 \
            int v = xv;                                                       \
            _Pragma("unroll")                                                 \
            for (int o = 1; o < 32; o <<= 1) {                                \
                int y = __shfl_up_sync(0xffffffffu, v, o);                    \
                if (lane >= o) v += y;                                        \
            }                                                                 \
            if (lane == 31) wsum[wid] = v;                                    \
            __syncthreads();                                                  \
            if (wid == 0) {                                                   \
                int w = (lane < NW) ? wsum[lane] : 0;                         \
                _Pragma("unroll")                                             \
                for (int o = 1; o < 16; o <<= 1) {                            \
                    int y = __shfl_up_sync(0xffffffffu, w, o);                \
                    if (lane >= o) w += y;                                    \
                }                                                             \
                if (lane < NW) wsum[lane] = w;                                \
            }                                                                 \
            __syncthreads();                                                  \
            int incl = v + (wid ? wsum[wid - 1] : 0);                         \
            P[tid] = incl - xv;                                               \
            if (tid == 383) {                                                 \
                P[384] = incl;                                                \
                P[385] = incl + hh[384];                                      \
                P[386] = P[385] + hh[385];                                    \
                P[387] = P[386] + hh[386];                                    \
            }                                                                 \
        }                                                                     \
        __syncthreads();                                                      \
        {                                                                     \
            int off = 0;                                                      \
            _Pragma("unroll")                                                 \
            for (int w = 0; w < NW; ++w)                                      \
                if (w < wid) off += (int)wpc[w * NCELL + idx];                \
            b[P[idx] + off + rank] = NH;                                      \
        }                                                                     \
        __syncthreads();                                                      \
    }

    const int r = tid;
    const float lin = (float)(-1.0 + 2.0 * (double)r / 383.0);
    const int loI = max(r - 7, 0), hiI = min(r + 10, NCELL);
    float sum_d2 = 0.0f;
    int idx, rank;

#pragma unroll 1
    for (int g = 0; g < G; ++g) {
        float e1, e2;
        ECT_BUCKET_PASS(acc1[g])
        {
            int lo = P[loI], hi = P[hiI];
            e1 = (float)lo;                    // saturated points
            for (int i = lo; i < hi; ++i) {
                float z = 500.0f * (lin - b[i]);
                z = fminf(fmaxf(z, -30.0f), 30.0f);
                e1 += __fdividef(1.0f, 1.0f + __expf(-z));
            }
        }
        ECT_BUCKET_PASS(acc2[g])
        {
            int lo = P[loI], hi = P[hiI];
            e2 = (float)lo;
            for (int i = lo; i < hi; ++i) {
                float z = 500.0f * (lin - b[i]);
                z = fminf(fmaxf(z, -30.0f), 30.0f);
                e2 += __fdividef(1.0f, 1.0f + __expf(-z));
            }
        }
        float d = e1 - e2;
        sum_d2 += d * d;
    }
#undef ECT_BUCKET_PASS

    // ---------- block reduce + deterministic cross-block finalize ----------
    red[r] = sum_d2;
    __syncthreads();
    if (r < 128) red[r] += red[r + 256];
    __syncthreads();
#pragma unroll
    for (int s = 128; s > 0; s >>= 1) {
        if (r < s) red[r] += red[r + s];
        __syncthreads();
    }

    if (r == 0) {
        unsigned long long q =
            (unsigned long long)llrint((double)red[0] * 4294967296.0);
        atomicAdd(&g_acc, q);
        __threadfence();
        unsigned int done = atomicAdd(&g_done, 1u);
        if (done == (unsigned int)(gridDim.x - 1)) {
            unsigned long long tot = atomicAdd(&g_acc, 0ULL);
            double loss = ((double)tot / 4294967296.0) / (double)(RES * T_DIRS);
            out[0] = (float)loss;
            for (int i = 1; i < out_size; ++i) out[i] = 0.0f;
            // reset for next graph replay
            atomicExch(&g_acc, 0ULL);
            atomicExch(&g_done, 0u);
        }
    }
}

extern "C" void kernel_launch(void* const* d_in, const int* in_sizes, int n_in,
                              void* d_out, int out_size) {
    const float* space1;
    const float* space2;
    if (in_sizes[0] == N_PTS * D1) {
        space1 = (const float*)d_in[0];
        space2 = (const float*)d_in[1];
    } else {
        space1 = (const float*)d_in[1];
        space2 = (const float*)d_in[0];
    }
    float* out = (float*)d_out;

    fused_kernel<<<GRID, 384>>>(space1, space2, out, out_size);
}

// round 14
// speedup vs baseline: 1.3292x; 1.3292x over previous
#include <cuda_runtime.h>
#include <cstdint>
#include <math.h>

#define T_DIRS 384
#define N_PTS  384
#define RES    384
#define D1     128
#define D2     32
#define NCELL  387    // cell idx 0..386 (cell -1 .. 385, +1 offset)
#define NW     12     // warps per block (384 threads)

__device__ unsigned long long g_acc;   // zero at load; reset by finalizer each replay
__device__ unsigned int g_done;

// ---------------- Threefry-2x32 (JAX), key = (0, 42) ----------------
__device__ __forceinline__ uint32_t rotl32(uint32_t x, int r) {
    return (x << r) | (x >> (32 - r));
}

__device__ __forceinline__ void threefry2x32_42(uint32_t c0, uint32_t c1,
                                                uint32_t& o0, uint32_t& o1) {
    const uint32_t k0 = 0u, k1 = 42u;
    const uint32_t k2 = 0x1BD11BDAu ^ k0 ^ k1;
    uint32_t x0 = c0 + k0, x1 = c1 + k1;
#define TF_GROUP(r0, r1, r2, r3, ka, kb, inc)                  \
    x0 += x1; x1 = rotl32(x1, r0); x1 ^= x0;                   \
    x0 += x1; x1 = rotl32(x1, r1); x1 ^= x0;                   \
    x0 += x1; x1 = rotl32(x1, r2); x1 ^= x0;                   \
    x0 += x1; x1 = rotl32(x1, r3); x1 ^= x0;                   \
    x0 += (ka); x1 += (kb) + (inc);
    TF_GROUP(13, 15, 26, 6,  k1, k2, 1u)
    TF_GROUP(17, 29, 16, 24, k2, k0, 2u)
    TF_GROUP(13, 15, 26, 6,  k0, k1, 3u)
    TF_GROUP(17, 29, 16, 24, k1, k2, 4u)
    TF_GROUP(13, 15, 26, 6,  k2, k0, 5u)
#undef TF_GROUP
    o0 = x0; o1 = x1;
}

// ---------------- XLA ErfInv (f32, Giles) ----------------
__device__ __forceinline__ float erfinv_xla(float x) {
    float w = -log1pf(-x * x);
    float p;
    if (w < 5.0f) {
        w -= 2.5f;
        p = 2.81022636e-08f;
        p = fmaf(p, w, 3.43273939e-07f);
        p = fmaf(p, w, -3.5233877e-06f);
        p = fmaf(p, w, -4.39150654e-06f);
        p = fmaf(p, w, 0.00021858087f);
        p = fmaf(p, w, -0.00125372503f);
        p = fmaf(p, w, -0.00417768164f);
        p = fmaf(p, w, 0.246640727f);
        p = fmaf(p, w, 1.50140941f);
    } else {
        w = sqrtf(w) - 3.0f;
        p = -0.000200214257f;
        p = fmaf(p, w, 0.000100950558f);
        p = fmaf(p, w, 0.00134934322f);
        p = fmaf(p, w, -0.00367342844f);
        p = fmaf(p, w, 0.00573950773f);
        p = fmaf(p, w, -0.0076224613f);
        p = fmaf(p, w, 0.00943887047f);
        p = fmaf(p, w, 1.00167406f);
        p = fmaf(p, w, 2.83297682f);
    }
    return p * x;
}

// Partitionable threefry: counter (0, j), 32-bit draw = y0 ^ y1.
__device__ __forceinline__ float jax_normal_elem(uint32_t j) {
    uint32_t o0, o1;
    threefry2x32_42(0u, j, o0, o1);
    uint32_t bits = o0 ^ o1;
    uint32_t fb = (bits >> 9) | 0x3f800000u;
    float f = __uint_as_float(fb) - 1.0f;
    const float lo = -0.99999994f;
    float u = f * 2.0f + lo;
    u = fmaxf(lo, u);
    return 1.41421356f * erfinv_xla(u);
}

// ===================== Single fused kernel =====================
// grid = 384 blocks (one per direction t), 384 threads (thread = point n = threshold r).
__global__ void __launch_bounds__(384) fused_kernel(const float* __restrict__ x1,
                                                    const float* __restrict__ x2,
                                                    float* __restrict__ out,
                                                    int out_size) {
    __shared__ float v1s[D1];                     // 512 B (normalized col)
    __shared__ float v2s[D2];                     // 128 B
    __shared__ unsigned short wpc[NW * NCELL];    // 9288 B per-warp cell counts
    __shared__ int   hh[NCELL];                   // 1548 B
    __shared__ int   P[NCELL + 1];                // 1552 B
    __shared__ float b[N_PTS];                    // 1536 B bucketed values
    __shared__ float nsq[4];
    __shared__ float wred[NW];
    __shared__ int   wsum[NW];

    const int tid  = threadIdx.x;
    const int t    = blockIdx.x;
    const int lane = tid & 31;
    const int wid  = tid >> 5;

    // ---------- Phase A: generate direction column t (both spaces) ----------
    // v2 (shape [32,384]) flat indices coincide with v1's first 32 rows -> reuse raws.
    if (tid < D1) {
        float raw = jax_normal_elem((uint32_t)(tid * T_DIRS + t));
        v1s[tid] = raw;
        float sq = raw * raw;
#pragma unroll
        for (int o = 16; o; o >>= 1) sq += __shfl_xor_sync(0xffffffffu, sq, o);
        if (lane == 0) nsq[wid] = sq;
    }
    __syncthreads();
    {
        const float nrm1 = sqrtf(nsq[0] + nsq[1] + nsq[2] + nsq[3]);
        const float nrm2 = sqrtf(nsq[0]);          // first 32 raws == v2 column
        if (tid < D1) {
            float raw = v1s[tid];
            if (tid < D2) v2s[tid] = raw / nrm2;
            v1s[tid] = raw / nrm1;
        }
    }
    __syncthreads();

    // ---------- Phase B: warp-per-point projections ----------
    // lane l holds v1[4l..4l+3] and v2[l] in registers; one coalesced LDG.128
    // per point per space; shuffle-reduce; lane p keeps point wid*32+p.
    float nh1 = 0.0f, nh2 = 0.0f;
    {
        const float4 vv1 = *reinterpret_cast<const float4*>(&v1s[4 * lane]);
        const float  vv2 = v2s[lane];
        const int nbase = wid * 32;
#pragma unroll 4
        for (int p = 0; p < 32; ++p) {
            const int n = nbase + p;
            float4 xq = __ldg(reinterpret_cast<const float4*>(x1 + n * D1) + lane);
            float s = xq.x * vv1.x;
            s = fmaf(xq.y, vv1.y, s);
            s = fmaf(xq.z, vv1.z, s);
            s = fmaf(xq.w, vv1.w, s);
            float s2 = __ldg(x2 + n * D2 + lane) * vv2;
#pragma unroll
            for (int o = 16; o; o >>= 1) {
                s  += __shfl_xor_sync(0xffffffffu, s,  o);
                s2 += __shfl_xor_sync(0xffffffffu, s2, o);
            }
            if (lane == p) { nh1 = s; nh2 = s2; }
        }
    }
    // now thread tid holds projections of point n = tid for both spaces.

    // ---------- Phase C/D: counting-sort ECT (threshold-grid cells) ----------
#define ECT_BUCKET_PASS(NH)                                                   \
    {                                                                         \
        for (int i = tid; i < (NW * NCELL) / 2; i += 384)                     \
            reinterpret_cast<int*>(wpc)[i] = 0;                               \
        __syncthreads();                                                      \
        int cc  = (int)floorf((NH + 1.0f) * 191.5f);                          \
        idx = min(max(cc, -1), 385) + 1;                                      \
        unsigned mmask = __match_any_sync(0xffffffffu, idx);                  \
        int leader = __ffs(mmask) - 1;                                        \
        rank = __popc(mmask & ((1u << lane) - 1u));                           \
        if (lane == leader)                                                   \
            wpc[wid * NCELL + idx] = (unsigned short)__popc(mmask);           \
        __syncthreads();                                                      \
        for (int i = tid; i < NCELL; i += 384) {                              \
            int ssum = 0;                                                     \
            _Pragma("unroll")                                                 \
            for (int w = 0; w < NW; ++w) ssum += (int)wpc[w * NCELL + i];     \
            hh[i] = ssum;                                                     \
        }                                                                     \
        __syncthreads();                                                      \
        {                                                                     \
            int xv = hh[tid];                                                 \
            int v = xv;                                                       \
            _Pragma("unroll")                                                 \
            for (int o = 1; o < 32; o <<= 1) {                                \
                int y = __shfl_up_sync(0xffffffffu, v, o);                    \
                if (lane >= o) v += y;                                        \
            }                                                                 \
            if (lane == 31) wsum[wid] = v;                                    \
            __syncthreads();                                                  \
            if (wid == 0) {                                                   \
                int w = (lane < NW) ? wsum[lane] : 0;                         \
                _Pragma("unroll")                                             \
                for (int o = 1; o < 16; o <<= 1) {                            \
                    int y = __shfl_up_sync(0xffffffffu, w, o);                \
                    if (lane >= o) w += y;                                    \
                }                                                             \
                if (lane < NW) wsum[lane] = w;                                \
            }                                                                 \
            __syncthreads();                                                  \
            int incl = v + (wid ? wsum[wid - 1] : 0);                         \
            P[tid] = incl - xv;                                               \
            if (tid == 383) {                                                 \
                P[384] = incl;                                                \
                P[385] = incl + hh[384];                                      \
                P[386] = P[385] + hh[385];                                    \
                P[387] = P[386] + hh[386];                                    \
            }                                                                 \
        }                                                                     \
        __syncthreads();                                                      \
        {                                                                     \
            int off = 0;                                                      \
            _Pragma("unroll")                                                 \
            for (int w = 0; w < NW; ++w)                                      \
                if (w < wid) off += (int)wpc[w * NCELL + idx];                \
            b[P[idx] + off + rank] = NH;                                      \
        }                                                                     \
        __syncthreads();                                                      \
    }

    const int r = tid;
    const float lin = (float)(-1.0 + 2.0 * (double)r / 383.0);
    const int loI = max(r - 7, 0), hiI = min(r + 10, NCELL);
    int idx, rank;
    float e1, e2;

    ECT_BUCKET_PASS(nh1)
    {
        int lo = P[loI], hi = P[hiI];
        e1 = (float)lo;                    // saturated (sigmoid≈1) points
        for (int i = lo; i < hi; ++i) {
            float z = 500.0f * (lin - b[i]);
            z = fminf(fmaxf(z, -30.0f), 30.0f);
            e1 += __fdividef(1.0f, 1.0f + __expf(-z));
        }
    }
    ECT_BUCKET_PASS(nh2)
    {
        int lo = P[loI], hi = P[hiI];
        e2 = (float)lo;
        for (int i = lo; i < hi; ++i) {
            float z = 500.0f * (lin - b[i]);
            z = fminf(fmaxf(z, -30.0f), 30.0f);
            e2 += __fdividef(1.0f, 1.0f + __expf(-z));
        }
    }
#undef ECT_BUCKET_PASS

    // ---------- block reduce of d^2 (warp shuffles + one smem round) ----------
    float d2 = (e1 - e2) * (e1 - e2);
#pragma unroll
    for (int o = 16; o; o >>= 1) d2 += __shfl_xor_sync(0xffffffffu, d2, o);
    if (lane == 0) wred[wid] = d2;
    __syncthreads();

    // ---------- deterministic cross-block finalize (fixed-point atomics) ----------
    if (wid == 0) {
        float v = (lane < NW) ? wred[lane] : 0.0f;
#pragma unroll
        for (int o = 8; o; o >>= 1) v += __shfl_xor_sync(0xffffffffu, v, o);
        if (lane == 0) {
            unsigned long long q =
                (unsigned long long)llrint((double)v * 4294967296.0);
            atomicAdd(&g_acc, q);
            __threadfence();
            unsigned int done = atomicAdd(&g_done, 1u);
            if (done == (unsigned int)(gridDim.x - 1)) {
                unsigned long long tot = atomicAdd(&g_acc, 0ULL);
                double loss = ((double)tot / 4294967296.0) / (double)(RES * T_DIRS);
                out[0] = (float)loss;
                for (int i = 1; i < out_size; ++i) out[i] = 0.0f;
                // reset for next graph replay
                atomicExch(&g_acc, 0ULL);
                atomicExch(&g_done, 0u);
            }
        }
    }
}

extern "C" void kernel_launch(void* const* d_in, const int* in_sizes, int n_in,
                              void* d_out, int out_size) {
    const float* space1;
    const float* space2;
    if (in_sizes[0] == N_PTS * D1) {
        space1 = (const float*)d_in[0];
        space2 = (const float*)d_in[1];
    } else {
        space1 = (const float*)d_in[1];
        space2 = (const float*)d_in[0];
    }
    float* out = (float*)d_out;

    fused_kernel<<<T_DIRS, 384>>>(space1, space2, out, out_size);
}